// round 9
// baseline (speedup 1.0000x reference)
#include <cuda_runtime.h>

// LocalInfoNCELoss, split-D with plain-store partial Grams:
// grid = 16 batches x 9 pixel-slices = 144 blocks (one wave).
// Each block: fused offset+gather (26x64 slice) -> 4x4-tiled partial Gram
// written DIRECTLY from registers to g_part[b][s][.] (no atomics, no smem
// staging). 9th finisher per batch: sum 9 partials (MLP=9 ldcg), norms,
// warp-per-row softmax. 16th finishing batch: sum, write out[0], reset.

#define BSZ    16
#define Hh     192
#define Ww     192
#define Cc     64
#define KKp    9
#define Rr     13
#define TWO_R  26
#define TAU_INV 2.0f
#define NPIX   9
#define N_TILES 7
#define N_TILE_PAIRS 28
#define SIMN   (TWO_R * TWO_R)     // 676

__device__ __align__(16) float g_part[BSZ][NPIX][SIMN];  // no reset needed
__device__ unsigned g_cnt[BSZ];
__device__ float    g_bloss[BSZ];
__device__ unsigned g_done;

__global__ __launch_bounds__(256, 1)
void infonce_split(const float* __restrict__ f1, const float* __restrict__ f2,
                   const int* __restrict__ bi, const int* __restrict__ hi,
                   const int* __restrict__ wi, float* __restrict__ out)
{
    __shared__ float p[28][Cc];            // 26 rows + 2 zero rows
    __shared__ float sim[SIMN];
    __shared__ float rn[32];
    __shared__ float rowloss[8];
    __shared__ int   s_last;

    const int blk  = blockIdx.x;
    const int b    = blk / NPIX;
    const int s    = blk - b * NPIX;       // pixel slice 0..8
    const int tid  = threadIdx.x;
    const int warp = tid >> 5;
    const int lane = tid & 31;

    // ---- Phase 1 (fused): per-thread offset + gather, zero-pad rows 26,27 ----
    #pragma unroll
    for (int it = 0; it < 2; it++) {
        int idx = tid + it * 256;
        if (idx < 28 * 16) {
            int i = idx >> 4, v = idx & 15;
            float4 val = make_float4(0.f, 0.f, 0.f, 0.f);
            if (i < TWO_R) {
                int r = (i < Rr) ? i : (i - Rr);
                int l = (r * BSZ + b) * KKp + s;
                int o = ((__ldg(bi + l) * Hh + __ldg(hi + l)) * Ww + __ldg(wi + l)) * Cc;
                const float* f = (i < Rr) ? f1 : f2;
                val = *(const float4*)(f + o + v * 4);
            }
            ((float4*)p[i])[v] = val;
        }
    }
    __syncthreads();

    // ---- Phase 2: partial Gram, 4x4 reg tiles, STG straight to g_part ----
    float* gp = &g_part[b][s][0];
    for (int t = warp; t < N_TILE_PAIRS; t += 8) {
        int ti = 0, tt = t;
        while (tt >= N_TILES - ti) { tt -= N_TILES - ti; ti++; }
        int tj = ti + tt;

        float acc[4][4];
        #pragma unroll
        for (int a = 0; a < 4; a++)
            #pragma unroll
            for (int c = 0; c < 4; c++) acc[a][c] = 0.f;

        #pragma unroll
        for (int it = 0; it < 2; it++) {
            int d = lane + it * 32;
            float av[4], bv[4];
            #pragma unroll
            for (int a = 0; a < 4; a++) av[a] = p[ti * 4 + a][d];
            #pragma unroll
            for (int c = 0; c < 4; c++) bv[c] = p[tj * 4 + c][d];
            #pragma unroll
            for (int a = 0; a < 4; a++)
                #pragma unroll
                for (int c = 0; c < 4; c++)
                    acc[a][c] = fmaf(av[a], bv[c], acc[a][c]);
        }
        #pragma unroll
        for (int a = 0; a < 4; a++) {
            #pragma unroll
            for (int c = 0; c < 4; c++) {
                float v = acc[a][c];
                #pragma unroll
                for (int o = 16; o > 0; o >>= 1)
                    v += __shfl_down_sync(0xffffffffu, v, o);
                if (lane == 0) {
                    int i = ti * 4 + a, j = tj * 4 + c;
                    if (i < TWO_R && j < TWO_R) {
                        gp[i * TWO_R + j] = v;
                        if (i != j) gp[j * TWO_R + i] = v;
                    }
                }
            }
        }
    }

    // ---- Phase 3: release stores, arrive on per-batch counter ----
    __threadfence();                        // release: all my STGs visible
    __syncthreads();
    if (tid == 0)
        s_last = (atomicAdd(&g_cnt[b], 1u) == NPIX - 1);
    __syncthreads();
    if (!s_last) return;

    // ---- Batch-last block: sum 9 partials (MLP=9), norms ----
    if (tid == 0) __threadfence();          // acquire pairing
    __syncthreads();
    if (tid < SIMN / 4) {                   // 169 float4 columns
        const float4* p0 = (const float4*)&g_part[b][0][0];
        float4 a = __ldcg(p0 + tid);
        #pragma unroll
        for (int r = 1; r < NPIX; r++) {
            float4 q = __ldcg(p0 + r * (SIMN / 4) + tid);
            a.x += q.x; a.y += q.y; a.z += q.z; a.w += q.w;
        }
        ((float4*)sim)[tid] = a;
    }
    if (tid == 0) g_cnt[b] = 0;             // reset for next replay
    __syncthreads();
    if (tid < TWO_R)
        rn[tid] = 1.f / fmaxf(sqrtf(sim[tid * TWO_R + tid]), 1e-8f);
    __syncthreads();

    // ---- Phase 4: per-row losses, warp per row (lane-parallel over j) ----
    float wl = 0.f;
    for (int i = warp; i < TWO_R; i += 8) {
        bool valid = (lane < TWO_R) && (lane != i);
        float v = valid ? sim[i * TWO_R + lane] * rn[i] * rn[lane] * TAU_INV
                        : -1e30f;
        float m = v;
        #pragma unroll
        for (int o = 16; o > 0; o >>= 1)
            m = fmaxf(m, __shfl_xor_sync(0xffffffffu, m, o));
        float e = valid ? __expf(v - m) : 0.f;
        #pragma unroll
        for (int o = 16; o > 0; o >>= 1)
            e += __shfl_xor_sync(0xffffffffu, e, o);
        int partner = (i + Rr) % TWO_R;
        float pv = __shfl_sync(0xffffffffu, v, partner);
        if (lane == 0) wl += __logf(e) + m - pv;
    }
    if (lane == 0) rowloss[warp] = wl;
    __syncthreads();

    // ---- Phase 5: batch loss; 16th finishing batch writes out & resets ----
    if (tid == 0) {
        float total = 0.f;
        #pragma unroll
        for (int k = 0; k < 8; k++) total += rowloss[k];
        g_bloss[b] = total;
        __threadfence();
        if (atomicAdd(&g_done, 1u) == BSZ - 1) {
            __threadfence();
            float tl = 0.f;
            #pragma unroll
            for (int k = 0; k < BSZ; k++) tl += __ldcg(&g_bloss[k]);
            out[0] = tl / (float)(BSZ * TWO_R);
            g_done = 0;
        }
    }
}

extern "C" void kernel_launch(void* const* d_in, const int* in_sizes, int n_in,
                              void* d_out, int out_size)
{
    const float* f1 = (const float*)d_in[0];
    const float* f2 = (const float*)d_in[1];
    const int*   bi = (const int*)d_in[2];
    const int*   hi = (const int*)d_in[3];
    const int*   wi = (const int*)d_in[4];
    float* out = (float*)d_out;

    infonce_split<<<BSZ * NPIX, 256>>>(f1, f2, bi, hi, wi, out);
}

// round 10
// speedup vs baseline: 1.1425x; 1.1425x over previous
#include <cuda_runtime.h>

// LocalInfoNCELoss, split-D (best skeleton) + butterfly Gram epilogue:
// grid = 16 batches x 9 pixel-slices = 144 blocks (one wave).
// Each block: fused offset+gather (26x64 slice) -> 4x4 reg-tiled partial Gram
// -> 31-shfl butterfly transpose-reduce -> 32-lane direct atomicAdd to
// g_sim[b] (incl. mirror). 9th finisher: vector reload, norms, no-max softmax.
// 16th finishing batch: writes out[0], resets.

#define BSZ    16
#define Hh     192
#define Ww     192
#define Cc     64
#define KKp    9
#define Rr     13
#define TWO_R  26
#define TAU_INV 2.0f
#define NPIX   9
#define N_TILES 7
#define N_TILE_PAIRS 28
#define SIMN   (TWO_R * TWO_R)     // 676

__device__ __align__(16) float g_sim[BSZ][SIMN];  // zero-init; reset each run
__device__ unsigned g_cnt[BSZ];
__device__ float    g_loss;
__device__ unsigned g_done;

__global__ __launch_bounds__(256, 1)
void infonce_split(const float* __restrict__ f1, const float* __restrict__ f2,
                   const int* __restrict__ bi, const int* __restrict__ hi,
                   const int* __restrict__ wi, float* __restrict__ out)
{
    __shared__ float p[28][Cc];            // 26 rows + 2 zero rows
    __shared__ float sim[SIMN];
    __shared__ float rn[32];
    __shared__ float rowloss[8];
    __shared__ int   s_last;

    const int blk  = blockIdx.x;
    const int b    = blk / NPIX;
    const int s    = blk - b * NPIX;       // pixel slice 0..8
    const int tid  = threadIdx.x;
    const int warp = tid >> 5;
    const int lane = tid & 31;

    // ---- Phase 1 (fused): per-thread offset + gather, zero-pad rows 26,27 ----
    #pragma unroll
    for (int it = 0; it < 2; it++) {
        int idx = tid + it * 256;
        if (idx < 28 * 16) {
            int i = idx >> 4, v = idx & 15;
            float4 val = make_float4(0.f, 0.f, 0.f, 0.f);
            if (i < TWO_R) {
                int r = (i < Rr) ? i : (i - Rr);
                int l = (r * BSZ + b) * KKp + s;
                int o = ((__ldg(bi + l) * Hh + __ldg(hi + l)) * Ww + __ldg(wi + l)) * Cc;
                const float* f = (i < Rr) ? f1 : f2;
                val = *(const float4*)(f + o + v * 4);
            }
            ((float4*)p[i])[v] = val;
        }
    }
    __syncthreads();

    // ---- Phase 2: partial Gram, 4x4 reg tiles, butterfly reduce, atomics ----
    for (int t = warp; t < N_TILE_PAIRS; t += 8) {
        int ti = 0, tt = t;
        while (tt >= N_TILES - ti) { tt -= N_TILES - ti; ti++; }
        int tj = ti + tt;

        float v[16];
        #pragma unroll
        for (int k = 0; k < 16; k++) v[k] = 0.f;

        #pragma unroll
        for (int it = 0; it < 2; it++) {
            int d = lane + it * 32;
            float av[4], bv[4];
            #pragma unroll
            for (int a = 0; a < 4; a++) av[a] = p[ti * 4 + a][d];
            #pragma unroll
            for (int c = 0; c < 4; c++) bv[c] = p[tj * 4 + c][d];
            #pragma unroll
            for (int a = 0; a < 4; a++)
                #pragma unroll
                for (int c = 0; c < 4; c++)
                    v[a * 4 + c] = fmaf(av[a], bv[c], v[a * 4 + c]);
        }

        // Butterfly transpose-reduce: 31 shfls; lane L ends with acc[L&15].
        #pragma unroll
        for (int k = 0; k < 16; k++)
            v[k] += __shfl_xor_sync(0xffffffffu, v[k], 16);
        int h3 = (lane >> 3) & 1;
        float w8[8];
        #pragma unroll
        for (int k = 0; k < 8; k++)
            w8[k] = v[h3 * 8 + k] + __shfl_xor_sync(0xffffffffu, v[(1 - h3) * 8 + k], 8);
        int h2 = (lane >> 2) & 1;
        float w4[4];
        #pragma unroll
        for (int k = 0; k < 4; k++)
            w4[k] = w8[h2 * 4 + k] + __shfl_xor_sync(0xffffffffu, w8[(1 - h2) * 4 + k], 4);
        int h1 = (lane >> 1) & 1;
        float w2[2];
        #pragma unroll
        for (int k = 0; k < 2; k++)
            w2[k] = w4[h1 * 2 + k] + __shfl_xor_sync(0xffffffffu, w4[(1 - h1) * 2 + k], 2);
        int h0 = lane & 1;
        float r = w2[h0] + __shfl_xor_sync(0xffffffffu, w2[1 - h0], 1);

        // lane L holds reduced acc for a=(L>>2)&3, c=L&3; lanes 16-31 mirror.
        int a = (lane >> 2) & 3, c = lane & 3;
        int i = ti * 4 + a, j = tj * 4 + c;
        if (i < TWO_R && j < TWO_R) {
            if (lane < 16)
                atomicAdd(&g_sim[b][i * TWO_R + j], r);
            else if (ti != tj)
                atomicAdd(&g_sim[b][j * TWO_R + i], r);
        }
    }

    // ---- Phase 3: release + arrive on per-batch counter ----
    __threadfence();
    __syncthreads();
    if (tid == 0)
        s_last = (atomicAdd(&g_cnt[b], 1u) == NPIX - 1);
    __syncthreads();
    if (!s_last) return;

    // ---- Batch-last block: vectorized reload + reset + norms ----
    float4* gs4 = (float4*)g_sim[b];
    if (tid < SIMN / 4)                       // 169 float4
        ((float4*)sim)[tid] = __ldcg((const float4*)gs4 + tid);
    __syncthreads();
    if (tid < SIMN / 4)
        gs4[tid] = make_float4(0.f, 0.f, 0.f, 0.f);
    if (tid == 0) g_cnt[b] = 0;
    if (tid < TWO_R)
        rn[tid] = 1.f / fmaxf(sqrtf(sim[tid * TWO_R + tid]), 1e-8f);
    __syncthreads();

    // ---- Phase 4: row losses, warp per row, NO max pass (|v| <= 2) ----
    float wl = 0.f;
    for (int i = warp; i < TWO_R; i += 8) {
        bool valid = (lane < TWO_R) && (lane != i);
        float v = valid ? sim[i * TWO_R + lane] * rn[i] * rn[lane] * TAU_INV
                        : 0.f;
        float e = valid ? __expf(v) : 0.f;
        #pragma unroll
        for (int o = 16; o > 0; o >>= 1)
            e += __shfl_xor_sync(0xffffffffu, e, o);
        int partner = (i + Rr) % TWO_R;
        float pv = __shfl_sync(0xffffffffu, v, partner);
        if (lane == 0) wl += __logf(e) - pv;
    }
    if (lane == 0) rowloss[warp] = wl;
    __syncthreads();

    // ---- Phase 5: batch loss; 16th finishing batch writes out & resets ----
    if (tid == 0) {
        float total = 0.f;
        #pragma unroll
        for (int k = 0; k < 8; k++) total += rowloss[k];
        atomicAdd(&g_loss, total);
        __threadfence();
        if (atomicAdd(&g_done, 1u) == BSZ - 1) {
            float tl = atomicAdd(&g_loss, 0.f);
            out[0] = tl / (float)(BSZ * TWO_R);
            g_loss = 0.f;
            g_done = 0;
        }
    }
}

extern "C" void kernel_launch(void* const* d_in, const int* in_sizes, int n_in,
                              void* d_out, int out_size)
{
    const float* f1 = (const float*)d_in[0];
    const float* f2 = (const float*)d_in[1];
    const int*   bi = (const int*)d_in[2];
    const int*   hi = (const int*)d_in[3];
    const int*   wi = (const int*)d_in[4];
    float* out = (float*)d_out;

    infonce_split<<<BSZ * NPIX, 256>>>(f1, f2, bi, hi, wi, out);
}

// round 13
// speedup vs baseline: 1.3881x; 1.2149x over previous
#include <cuda_runtime.h>

// LocalInfoNCELoss, split-D champion skeleton + dot-row Gram (R9 fixed):
// grid = 16 batches x 9 pixel-slices = 144 blocks (one wave).
// Each block: fused offset+gather (26x64 slice, stride-68 smem, FULL 2-iter
// loop) -> warp-per-4-rows dot products (LDS.128, no shuffles) ->
// register->atomicAdd into g_sim[b]. 9th finisher: vector reload, inline
// norms, no-max softmax. 16th finishing batch: writes out[0], resets.

#define BSZ    16
#define Hh     192
#define Ww     192
#define Cc     64
#define KKp    9
#define Rr     13
#define TWO_R  26
#define TAU_INV 2.0f
#define NPIX   9
#define SIMN   (TWO_R * TWO_R)     // 676
#define STRD   68                  // padded row stride (floats): conflict-free

__device__ __align__(16) float g_sim[BSZ][SIMN];  // zero-init; reset each run
__device__ unsigned g_cnt[BSZ];
__device__ float    g_loss;
__device__ unsigned g_done;

__global__ __launch_bounds__(256, 1)
void infonce_split(const float* __restrict__ f1, const float* __restrict__ f2,
                   const int* __restrict__ bi, const int* __restrict__ hi,
                   const int* __restrict__ wi, float* __restrict__ out)
{
    __shared__ __align__(16) float p[32][STRD];   // rows 26..31 zeroed (cols 0..63)
    __shared__ float sim[SIMN];
    __shared__ float rowloss[8];
    __shared__ int   s_last;

    const int blk  = blockIdx.x;
    const int b    = blk / NPIX;
    const int s    = blk - b * NPIX;       // pixel slice 0..8
    const int tid  = threadIdx.x;
    const int warp = tid >> 5;
    const int lane = tid & 31;

    // ---- Phase 1 (fused): offsets + gather. 512 items = 416 gather + 96 pad ----
    #pragma unroll
    for (int it = 0; it < 2; it++) {
        int idx = tid + it * 256;
        if (idx < TWO_R * 16) {
            int i = idx >> 4, v = idx & 15;
            int r = (i < Rr) ? i : (i - Rr);
            int l = (r * BSZ + b) * KKp + s;
            int o = ((__ldg(bi + l) * Hh + __ldg(hi + l)) * Ww + __ldg(wi + l)) * Cc;
            const float* f = (i < Rr) ? f1 : f2;
            float4 val = *(const float4*)(f + o + v * 4);
            ((float4*)p[i])[v] = val;
        } else {
            int z = idx - TWO_R * 16;          // 0..95 : zero rows 26..31, cols 0..63
            if (z < 96) {
                int i = 26 + (z >> 4), v = z & 15;
                ((float4*)p[i])[v] = make_float4(0.f, 0.f, 0.f, 0.f);
            }
        }
    }
    __syncthreads();

    // ---- Phase 2: dot-row Gram. warp w -> rows {w, w+8, w+16, w+24} ----
    {
        const int i0 = warp, i1 = warp + 8, i2 = warp + 16, i3 = warp + 24;
        float a0 = 0.f, a1 = 0.f, a2 = 0.f, a3 = 0.f;
        #pragma unroll
        for (int d4 = 0; d4 < 16; d4++) {
            float4 vj = ((const float4*)p[lane])[d4];
            float4 r0 = ((const float4*)p[i0])[d4];
            float4 r1 = ((const float4*)p[i1])[d4];
            float4 r2 = ((const float4*)p[i2])[d4];
            float4 r3 = ((const float4*)p[i3])[d4];
            a0 = fmaf(r0.x, vj.x, a0); a0 = fmaf(r0.y, vj.y, a0);
            a0 = fmaf(r0.z, vj.z, a0); a0 = fmaf(r0.w, vj.w, a0);
            a1 = fmaf(r1.x, vj.x, a1); a1 = fmaf(r1.y, vj.y, a1);
            a1 = fmaf(r1.z, vj.z, a1); a1 = fmaf(r1.w, vj.w, a1);
            a2 = fmaf(r2.x, vj.x, a2); a2 = fmaf(r2.y, vj.y, a2);
            a2 = fmaf(r2.z, vj.z, a2); a2 = fmaf(r2.w, vj.w, a2);
            a3 = fmaf(r3.x, vj.x, a3); a3 = fmaf(r3.y, vj.y, a3);
            a3 = fmaf(r3.z, vj.z, a3); a3 = fmaf(r3.w, vj.w, a3);
        }
        if (lane < TWO_R) {
            float* gs = g_sim[b];
            atomicAdd(&gs[i0 * TWO_R + lane], a0);
            atomicAdd(&gs[i1 * TWO_R + lane], a1);
            atomicAdd(&gs[i2 * TWO_R + lane], a2);
            if (i3 < TWO_R)
                atomicAdd(&gs[i3 * TWO_R + lane], a3);
        }
    }

    // ---- Phase 3: release + arrive on per-batch counter ----
    __threadfence();
    __syncthreads();
    if (tid == 0)
        s_last = (atomicAdd(&g_cnt[b], 1u) == NPIX - 1);
    __syncthreads();
    if (!s_last) return;

    // ---- Batch-last block: vectorized reload + reset ----
    float4* gs4 = (float4*)g_sim[b];
    if (tid < SIMN / 4)                       // 169 float4
        ((float4*)sim)[tid] = __ldcg((const float4*)gs4 + tid);
    __syncthreads();
    if (tid < SIMN / 4)
        gs4[tid] = make_float4(0.f, 0.f, 0.f, 0.f);
    if (tid == 0) g_cnt[b] = 0;
    __syncthreads();

    // ---- Phase 4: row losses, inline rn, no max pass (|v| <= 2) ----
    {
        int jj = (lane < TWO_R) ? lane : 25;
        float rn_j = 1.f / fmaxf(sqrtf(sim[jj * TWO_R + jj]), 1e-8f);
        float wl = 0.f;
        #pragma unroll
        for (int ri = 0; ri < 4; ri++) {
            int i = warp + ri * 8;
            if (i < TWO_R) {
                float rn_i = __shfl_sync(0xffffffffu, rn_j, i);
                bool valid = (lane < TWO_R) && (lane != i);
                float v = valid ? sim[i * TWO_R + lane] * rn_i * rn_j * TAU_INV
                                : 0.f;
                float e = valid ? __expf(v) : 0.f;
                #pragma unroll
                for (int o = 16; o > 0; o >>= 1)
                    e += __shfl_xor_sync(0xffffffffu, e, o);
                int partner = (i + Rr) % TWO_R;
                float pv = __shfl_sync(0xffffffffu, v, partner);
                if (lane == 0) wl += __logf(e) - pv;
            }
        }
        if (lane == 0) rowloss[warp] = wl;
    }
    __syncthreads();

    // ---- Phase 5: batch loss; 16th finishing batch writes out & resets ----
    if (tid == 0) {
        float total = 0.f;
        #pragma unroll
        for (int k = 0; k < 8; k++) total += rowloss[k];
        atomicAdd(&g_loss, total);
        __threadfence();
        if (atomicAdd(&g_done, 1u) == BSZ - 1) {
            float tl = atomicAdd(&g_loss, 0.f);
            out[0] = tl / (float)(BSZ * TWO_R);
            g_loss = 0.f;
            g_done = 0;
        }
    }
}

extern "C" void kernel_launch(void* const* d_in, const int* in_sizes, int n_in,
                              void* d_out, int out_size)
{
    const float* f1 = (const float*)d_in[0];
    const float* f2 = (const float*)d_in[1];
    const int*   bi = (const int*)d_in[2];
    const int*   hi = (const int*)d_in[3];
    const int*   wi = (const int*)d_in[4];
    float* out = (float*)d_out;

    infonce_split<<<BSZ * NPIX, 256>>>(f1, f2, bi, hi, wi, out);
}

// round 14
// speedup vs baseline: 1.4220x; 1.0245x over previous
#include <cuda_runtime.h>

// LocalInfoNCELoss, split-D + dot-row Gram, 512-thread blocks, fused
// double-atomic global finish.
// grid = 16 batches x 9 pixel-slices = 144 blocks (one wave).

#define BSZ    16
#define Hh     192
#define Ww     192
#define Cc     64
#define KKp    9
#define Rr     13
#define TWO_R  26
#define TAU_INV 2.0f
#define NPIX   9
#define SIMN   (TWO_R * TWO_R)     // 676
#define STRD   68                  // padded row stride (floats)
#define OFS    1099511627776.0     // 2^40 arrival marker

__device__ __align__(16) float g_sim[BSZ][SIMN];  // zero-init; reset each run
__device__ unsigned g_cnt[BSZ];
__device__ double   g_dsum;                        // fused count+sum

__global__ __launch_bounds__(512, 1)
void infonce_split(const float* __restrict__ f1, const float* __restrict__ f2,
                   const int* __restrict__ bi, const int* __restrict__ hi,
                   const int* __restrict__ wi, float* __restrict__ out)
{
    __shared__ __align__(16) float p[32][STRD];   // rows 26..31 zeroed (cols 0..63)
    __shared__ float sim[SIMN];
    __shared__ float rowloss[16];
    __shared__ int   s_last;

    const int blk  = blockIdx.x;
    const int b    = blk / NPIX;
    const int s    = blk - b * NPIX;       // pixel slice 0..8
    const int tid  = threadIdx.x;
    const int warp = tid >> 5;             // 0..15
    const int lane = tid & 31;

    // ---- Phase 1: offsets + gather, one item per thread (416 + 96 pad) ----
    if (tid < TWO_R * 16) {
        int i = tid >> 4, v = tid & 15;
        int r = (i < Rr) ? i : (i - Rr);
        int l = (r * BSZ + b) * KKp + s;
        int o = ((__ldg(bi + l) * Hh + __ldg(hi + l)) * Ww + __ldg(wi + l)) * Cc;
        const float* f = (i < Rr) ? f1 : f2;
        ((float4*)p[i])[v] = *(const float4*)(f + o + v * 4);
    } else {
        int z = tid - TWO_R * 16;          // 0..95: zero rows 26..31, 16 float4 each
        int i = 26 + (z >> 4), v = z & 15;
        ((float4*)p[i])[v] = make_float4(0.f, 0.f, 0.f, 0.f);
    }
    __syncthreads();

    // ---- Phase 2: dot-row Gram. warp w -> rows {w, w+16} ----
    {
        const int i0 = warp, i1 = warp + 16;
        float a0 = 0.f, a1 = 0.f;
        #pragma unroll
        for (int d4 = 0; d4 < 16; d4++) {
            float4 vj = ((const float4*)p[lane])[d4];
            float4 r0 = ((const float4*)p[i0])[d4];
            float4 r1 = ((const float4*)p[i1])[d4];
            a0 = fmaf(r0.x, vj.x, a0); a0 = fmaf(r0.y, vj.y, a0);
            a0 = fmaf(r0.z, vj.z, a0); a0 = fmaf(r0.w, vj.w, a0);
            a1 = fmaf(r1.x, vj.x, a1); a1 = fmaf(r1.y, vj.y, a1);
            a1 = fmaf(r1.z, vj.z, a1); a1 = fmaf(r1.w, vj.w, a1);
        }
        if (lane < TWO_R) {
            float* gs = g_sim[b];
            atomicAdd(&gs[i0 * TWO_R + lane], a0);
            if (i1 < TWO_R)
                atomicAdd(&gs[i1 * TWO_R + lane], a1);
        }
    }

    // ---- Phase 3: release + arrive on per-batch counter ----
    __threadfence();
    __syncthreads();
    if (tid == 0)
        s_last = (atomicAdd(&g_cnt[b], 1u) == NPIX - 1);
    __syncthreads();
    if (!s_last) return;

    // ---- Batch-last block: vectorized reload + reset ----
    float4* gs4 = (float4*)g_sim[b];
    if (tid < SIMN / 4)                       // 169 float4
        ((float4*)sim)[tid] = __ldcg((const float4*)gs4 + tid);
    __syncthreads();
    if (tid < SIMN / 4)
        gs4[tid] = make_float4(0.f, 0.f, 0.f, 0.f);
    if (tid == 0) g_cnt[b] = 0;
    __syncthreads();

    // ---- Phase 4: row losses, inline rn, no max pass (|v| <= 2) ----
    {
        int jj = (lane < TWO_R) ? lane : 25;
        float rn_j = 1.f / fmaxf(sqrtf(sim[jj * TWO_R + jj]), 1e-8f);
        float wl = 0.f;
        #pragma unroll
        for (int ri = 0; ri < 2; ri++) {
            int i = warp + ri * 16;
            if (i < TWO_R) {
                float rn_i = __shfl_sync(0xffffffffu, rn_j, i);
                bool valid = (lane < TWO_R) && (lane != i);
                float v = valid ? sim[i * TWO_R + lane] * rn_i * rn_j * TAU_INV
                                : 0.f;
                float e = valid ? __expf(v) : 0.f;
                #pragma unroll
                for (int o = 16; o > 0; o >>= 1)
                    e += __shfl_xor_sync(0xffffffffu, e, o);
                int partner = (i + Rr) % TWO_R;
                float pv = __shfl_sync(0xffffffffu, v, partner);
                if (lane == 0) wl += __logf(e) - pv;
            }
        }
        if (lane == 0) rowloss[warp] = wl;
    }
    __syncthreads();

    // ---- Phase 5: ONE fused atomic: count in high bits, sum in low ----
    if (tid == 0) {
        float total = 0.f;
        #pragma unroll
        for (int k = 0; k < 16; k++) total += rowloss[k];
        double old = atomicAdd(&g_dsum, (double)total + OFS);
        if (old >= 15.0 * OFS) {               // I'm the 16th finisher
            double full = old + (double)total + OFS - 16.0 * OFS;
            out[0] = (float)(full / (double)(BSZ * TWO_R));
            g_dsum = 0.0;                       // reset for next replay
        }
    }
}

extern "C" void kernel_launch(void* const* d_in, const int* in_sizes, int n_in,
                              void* d_out, int out_size)
{
    const float* f1 = (const float*)d_in[0];
    const float* f2 = (const float*)d_in[1];
    const int*   bi = (const int*)d_in[2];
    const int*   hi = (const int*)d_in[3];
    const int*   wi = (const int*)d_in[4];
    float* out = (float*)d_out;

    infonce_split<<<BSZ * NPIX, 512>>>(f1, f2, bi, hi, wi, out);
}

// round 15
// speedup vs baseline: 1.5347x; 1.0792x over previous
#include <cuda_runtime.h>

// LocalInfoNCELoss, split-D + dot-row Gram, 512-thread blocks,
// release/acquire counter (no block-wide threadfence), fused double-atomic
// global finish. grid = 16 batches x 9 pixel-slices = 144 blocks (one wave).

#define BSZ    16
#define Hh     192
#define Ww     192
#define Cc     64
#define KKp    9
#define Rr     13
#define TWO_R  26
#define TAU_INV 2.0f
#define NPIX   9
#define SIMN   (TWO_R * TWO_R)     // 676
#define STRD   68                  // padded row stride (floats)
#define OFS    1099511627776.0     // 2^40 arrival marker

__device__ __align__(16) float g_sim[BSZ][SIMN];  // zero-init; reset each run
__device__ unsigned g_cnt[BSZ];
__device__ double   g_dsum;                        // fused count+sum

__device__ __forceinline__ unsigned atom_add_acqrel_gpu(unsigned* a, unsigned v)
{
    unsigned old;
    asm volatile("atom.add.acq_rel.gpu.u32 %0, [%1], %2;"
                 : "=r"(old) : "l"(a), "r"(v) : "memory");
    return old;
}

__global__ __launch_bounds__(512, 1)
void infonce_split(const float* __restrict__ f1, const float* __restrict__ f2,
                   const int* __restrict__ bi, const int* __restrict__ hi,
                   const int* __restrict__ wi, float* __restrict__ out)
{
    __shared__ __align__(16) float p[32][STRD];   // rows 26..31 never validly read
    __shared__ float sim[SIMN];
    __shared__ float rowloss[16];
    __shared__ int   s_last;

    const int blk  = blockIdx.x;
    const int b    = blk / NPIX;
    const int s    = blk - b * NPIX;       // pixel slice 0..8
    const int tid  = threadIdx.x;
    const int warp = tid >> 5;             // 0..15
    const int lane = tid & 31;

    // ---- Phase 1: offsets + gather, one float4 per thread (416 active) ----
    if (tid < TWO_R * 16) {
        int i = tid >> 4, v = tid & 15;
        int r = (i < Rr) ? i : (i - Rr);
        int l = (r * BSZ + b) * KKp + s;
        int o = ((__ldg(bi + l) * Hh + __ldg(hi + l)) * Ww + __ldg(wi + l)) * Cc;
        const float* f = (i < Rr) ? f1 : f2;
        ((float4*)p[i])[v] = *(const float4*)(f + o + v * 4);
    }
    __syncthreads();

    // ---- Phase 2: dot-row Gram. warp w -> rows {w, w+16} ----
    // Lanes >= 26 and rows >= 26 read garbage smem into accumulators that the
    // guards below discard — never added to live data.
    {
        const int i0 = warp, i1 = warp + 16;
        float a0 = 0.f, a1 = 0.f;
        #pragma unroll
        for (int d4 = 0; d4 < 16; d4++) {
            float4 vj = ((const float4*)p[lane])[d4];
            float4 r0 = ((const float4*)p[i0])[d4];
            float4 r1 = ((const float4*)p[i1])[d4];
            a0 = fmaf(r0.x, vj.x, a0); a0 = fmaf(r0.y, vj.y, a0);
            a0 = fmaf(r0.z, vj.z, a0); a0 = fmaf(r0.w, vj.w, a0);
            a1 = fmaf(r1.x, vj.x, a1); a1 = fmaf(r1.y, vj.y, a1);
            a1 = fmaf(r1.z, vj.z, a1); a1 = fmaf(r1.w, vj.w, a1);
        }
        if (lane < TWO_R) {
            float* gs = g_sim[b];
            atomicAdd(&gs[i0 * TWO_R + lane], a0);
            if (i1 < TWO_R)
                atomicAdd(&gs[i1 * TWO_R + lane], a1);
        }
    }

    // ---- Phase 3: acq_rel counter arrive (no block-wide fence) ----
    // syncthreads gives CTA-scope hb from every thread's atomics to tid0's
    // release; acq_rel transfers the cumulative set to the consumer.
    __syncthreads();
    if (tid == 0)
        s_last = (atom_add_acqrel_gpu(&g_cnt[b], 1u) == NPIX - 1);
    __syncthreads();
    if (!s_last) return;

    // ---- Batch-last block: vectorized reload; reset off the critical path ----
    float4* gs4 = (float4*)g_sim[b];
    if (tid < SIMN / 4)                       // 169 float4
        ((float4*)sim)[tid] = __ldcg((const float4*)gs4 + tid);
    __syncthreads();
    if (tid < SIMN / 4)
        gs4[tid] = make_float4(0.f, 0.f, 0.f, 0.f);
    if (tid == 0) g_cnt[b] = 0;
    // no barrier needed: reset stores don't alias sim[]

    // ---- Phase 4: row losses, inline rn, no max pass (|v| <= 2) ----
    {
        int jj = (lane < TWO_R) ? lane : 25;
        float rn_j = 1.f / fmaxf(sqrtf(sim[jj * TWO_R + jj]), 1e-8f);
        float wl = 0.f;
        #pragma unroll
        for (int ri = 0; ri < 2; ri++) {
            int i = warp + ri * 16;
            if (i < TWO_R) {
                float rn_i = __shfl_sync(0xffffffffu, rn_j, i);
                bool valid = (lane < TWO_R) && (lane != i);
                float v = valid ? sim[i * TWO_R + lane] * rn_i * rn_j * TAU_INV
                                : 0.f;
                float e = valid ? __expf(v) : 0.f;
                #pragma unroll
                for (int o = 16; o > 0; o >>= 1)
                    e += __shfl_xor_sync(0xffffffffu, e, o);
                int partner = (i + Rr) % TWO_R;
                float pv = __shfl_sync(0xffffffffu, v, partner);
                if (lane == 0) wl += __logf(e) - pv;
            }
        }
        if (lane == 0) rowloss[warp] = wl;
    }
    __syncthreads();

    // ---- Phase 5: ONE fused atomic: count in high bits, sum in low ----
    if (tid == 0) {
        float total = 0.f;
        #pragma unroll
        for (int k = 0; k < 16; k++) total += rowloss[k];
        double old = atomicAdd(&g_dsum, (double)total + OFS);
        if (old >= 15.0 * OFS) {               // I'm the 16th finisher
            double full = old + (double)total + OFS - 16.0 * OFS;
            out[0] = (float)(full / (double)(BSZ * TWO_R));
            g_dsum = 0.0;                       // reset for next replay
        }
    }
}

extern "C" void kernel_launch(void* const* d_in, const int* in_sizes, int n_in,
                              void* d_out, int out_size)
{
    const float* f1 = (const float*)d_in[0];
    const float* f2 = (const float*)d_in[1];
    const int*   bi = (const int*)d_in[2];
    const int*   hi = (const int*)d_in[3];
    const int*   wi = (const int*)d_in[4];
    float* out = (float*)d_out;

    infonce_split<<<BSZ * NPIX, 512>>>(f1, f2, bi, hi, wi, out);
}

// round 16
// speedup vs baseline: 1.6667x; 1.0860x over previous
#include <cuda_runtime.h>

// LocalInfoNCELoss, split-D + dot-row Gram, 512-thread blocks,
// acq_rel counter, direct-ldcg tail (no smem staging), fused double-atomic
// finish. grid = 16 batches x 9 pixel-slices = 144 blocks (one wave).

#define BSZ    16
#define Hh     192
#define Ww     192
#define Cc     64
#define KKp    9
#define Rr     13
#define TWO_R  26
#define TAU_INV 2.0f
#define NPIX   9
#define SIMN   (TWO_R * TWO_R)     // 676
#define STRD   68                  // padded row stride (floats)
#define OFS    1099511627776.0     // 2^40 arrival marker

__device__ __align__(16) float g_sim[BSZ][SIMN];  // zero-init; reset each run
__device__ unsigned g_cnt[BSZ];
__device__ double   g_dsum;                        // fused count+sum

__device__ __forceinline__ unsigned atom_add_acqrel_gpu(unsigned* a, unsigned v)
{
    unsigned old;
    asm volatile("atom.add.acq_rel.gpu.u32 %0, [%1], %2;"
                 : "=r"(old) : "l"(a), "r"(v) : "memory");
    return old;
}

__global__ __launch_bounds__(512, 1)
void infonce_split(const float* __restrict__ f1, const float* __restrict__ f2,
                   const int* __restrict__ bi, const int* __restrict__ hi,
                   const int* __restrict__ wi, float* __restrict__ out)
{
    __shared__ __align__(16) float p[32][STRD];   // rows 26..31 never validly read
    __shared__ float rowloss[16];
    __shared__ int   s_last;

    const int blk  = blockIdx.x;
    const int b    = blk / NPIX;
    const int s    = blk - b * NPIX;       // pixel slice 0..8
    const int tid  = threadIdx.x;
    const int warp = tid >> 5;             // 0..15
    const int lane = tid & 31;

    // ---- Phase 1: offsets + gather, one float4 per thread (416 active) ----
    if (tid < TWO_R * 16) {
        int i = tid >> 4, v = tid & 15;
        int r = (i < Rr) ? i : (i - Rr);
        int l = (r * BSZ + b) * KKp + s;
        int o = ((__ldg(bi + l) * Hh + __ldg(hi + l)) * Ww + __ldg(wi + l)) * Cc;
        const float* f = (i < Rr) ? f1 : f2;
        ((float4*)p[i])[v] = *(const float4*)(f + o + v * 4);
    }
    __syncthreads();

    // ---- Phase 2: dot-row Gram. warp w -> rows {w, w+16} ----
    // Lanes/rows >= 26 accumulate garbage that the guards below discard.
    {
        const int i0 = warp, i1 = warp + 16;
        float a0 = 0.f, a1 = 0.f;
        #pragma unroll
        for (int d4 = 0; d4 < 16; d4++) {
            float4 vj = ((const float4*)p[lane])[d4];
            float4 r0 = ((const float4*)p[i0])[d4];
            float4 r1 = ((const float4*)p[i1])[d4];
            a0 = fmaf(r0.x, vj.x, a0); a0 = fmaf(r0.y, vj.y, a0);
            a0 = fmaf(r0.z, vj.z, a0); a0 = fmaf(r0.w, vj.w, a0);
            a1 = fmaf(r1.x, vj.x, a1); a1 = fmaf(r1.y, vj.y, a1);
            a1 = fmaf(r1.z, vj.z, a1); a1 = fmaf(r1.w, vj.w, a1);
        }
        if (lane < TWO_R) {
            float* gs = g_sim[b];
            atomicAdd(&gs[i0 * TWO_R + lane], a0);
            if (i1 < TWO_R)
                atomicAdd(&gs[i1 * TWO_R + lane], a1);
        }
    }

    // ---- Phase 3: acq_rel counter arrive (no block-wide fence) ----
    __syncthreads();
    if (tid == 0)
        s_last = (atom_add_acqrel_gpu(&g_cnt[b], 1u) == NPIX - 1);
    __syncthreads();
    if (!s_last) return;

    // ---- Phase 4 (batch-last): row losses straight from g_sim via ldcg ----
    {
        const float* gs = g_sim[b];
        int jj = (lane < TWO_R) ? lane : 25;
        float dj = __ldcg(gs + 27 * jj);                 // diag[jj]
        float v0r = __ldcg(gs + warp * TWO_R + jj);      // row warp, col jj
        float v1r = (warp + 16 < TWO_R)
                  ? __ldcg(gs + (warp + 16) * TWO_R + jj) : 0.f;
        float rn_j = rsqrtf(fmaxf(dj, 1e-16f));

        float wl = 0.f;
        #pragma unroll
        for (int ri = 0; ri < 2; ri++) {
            int i = warp + ri * 16;
            if (i < TWO_R) {
                float raw = ri ? v1r : v0r;
                float rn_i = __shfl_sync(0xffffffffu, rn_j, i);
                bool valid = (lane < TWO_R) && (lane != i);
                float v = valid ? raw * rn_i * rn_j * TAU_INV : 0.f;
                float e = valid ? __expf(v) : 0.f;
                #pragma unroll
                for (int o = 16; o > 0; o >>= 1)
                    e += __shfl_xor_sync(0xffffffffu, e, o);
                int partner = (i + Rr) % TWO_R;
                float pv = __shfl_sync(0xffffffffu, v, partner);
                if (lane == 0) wl += __logf(e) - pv;
            }
        }
        if (lane == 0) rowloss[warp] = wl;
    }
    __syncthreads();   // orders rowloss AND all phase-4 ldcg before the reset

    // ---- Reset g_sim[b] + counter (after all reads done) ----
    if (tid < SIMN / 4)
        ((float4*)g_sim[b])[tid] = make_float4(0.f, 0.f, 0.f, 0.f);
    if (tid == 1) g_cnt[b] = 0;

    // ---- Phase 5: ONE fused atomic: count in high bits, sum in low ----
    if (tid == 0) {
        float total = 0.f;
        #pragma unroll
        for (int k = 0; k < 16; k++) total += rowloss[k];
        double old = atomicAdd(&g_dsum, (double)total + OFS);
        if (old >= 15.0 * OFS) {               // I'm the 16th finisher
            double full = old + (double)total + OFS - 16.0 * OFS;
            out[0] = (float)(full / (double)(BSZ * TWO_R));
            g_dsum = 0.0;                       // reset for next replay
        }
    }
}

extern "C" void kernel_launch(void* const* d_in, const int* in_sizes, int n_in,
                              void* d_out, int out_size)
{
    const float* f1 = (const float*)d_in[0];
    const float* f2 = (const float*)d_in[1];
    const int*   bi = (const int*)d_in[2];
    const int*   hi = (const int*)d_in[3];
    const int*   wi = (const int*)d_in[4];
    float* out = (float*)d_out;

    infonce_split<<<BSZ * NPIX, 512>>>(f1, f2, bi, hi, wi, out);
}

// round 17
// speedup vs baseline: 1.7096x; 1.0257x over previous
#include <cuda_runtime.h>

// LocalInfoNCELoss, split-D + dot-row Gram (4 warps x 7 rows), 512-thread
// blocks, acq_rel counter, direct-ldcg tail, fused double-atomic finish.
// grid = 16 batches x 9 pixel-slices = 144 blocks (one wave).

#define BSZ    16
#define Hh     192
#define Ww     192
#define Cc     64
#define KKp    9
#define Rr     13
#define TWO_R  26
#define TAU_INV 2.0f
#define NPIX   9
#define SIMN   (TWO_R * TWO_R)     // 676
#define STRD   68                  // padded row stride (floats)
#define OFS    1099511627776.0     // 2^40 arrival marker

__device__ __align__(16) float g_sim[BSZ][SIMN];  // zero-init; reset each run
__device__ unsigned g_cnt[BSZ];
__device__ double   g_dsum;                        // fused count+sum

__device__ __forceinline__ unsigned atom_add_acqrel_gpu(unsigned* a, unsigned v)
{
    unsigned old;
    asm volatile("atom.add.acq_rel.gpu.u32 %0, [%1], %2;"
                 : "=r"(old) : "l"(a), "r"(v) : "memory");
    return old;
}

__global__ __launch_bounds__(512, 1)
void infonce_split(const float* __restrict__ f1, const float* __restrict__ f2,
                   const int* __restrict__ bi, const int* __restrict__ hi,
                   const int* __restrict__ wi, float* __restrict__ out)
{
    __shared__ __align__(16) float p[32][STRD];   // rows 26..31 never validly read
    __shared__ float rowloss[16];
    __shared__ int   s_last;

    const int blk  = blockIdx.x;
    const int b    = blk / NPIX;
    const int s    = blk - b * NPIX;       // pixel slice 0..8
    const int tid  = threadIdx.x;
    const int warp = tid >> 5;             // 0..15
    const int lane = tid & 31;

    // ---- Phase 1: offsets + gather, one float4 per thread (416 active) ----
    if (tid < TWO_R * 16) {
        int i = tid >> 4, v = tid & 15;
        int r = (i < Rr) ? i : (i - Rr);
        int l = (r * BSZ + b) * KKp + s;
        int o = ((__ldg(bi + l) * Hh + __ldg(hi + l)) * Ww + __ldg(wi + l)) * Cc;
        const float* f = (i < Rr) ? f1 : f2;
        ((float4*)p[i])[v] = *(const float4*)(f + o + v * 4);
    }
    __syncthreads();

    // ---- Phase 2: dot-row Gram, warps 0-3 only, 7 rows each (28 >= 26) ----
    // Rows/lanes >= 26 accumulate garbage that the guards below discard.
    if (warp < 4) {
        const int i0 = warp * 7;
        float acc[7];
        #pragma unroll
        for (int k = 0; k < 7; k++) acc[k] = 0.f;

        #pragma unroll
        for (int d4 = 0; d4 < 16; d4++) {
            float4 vj = ((const float4*)p[lane])[d4];
            #pragma unroll
            for (int k = 0; k < 7; k++) {
                float4 rk = ((const float4*)p[i0 + k])[d4];
                acc[k] = fmaf(rk.x, vj.x, acc[k]);
                acc[k] = fmaf(rk.y, vj.y, acc[k]);
                acc[k] = fmaf(rk.z, vj.z, acc[k]);
                acc[k] = fmaf(rk.w, vj.w, acc[k]);
            }
        }
        if (lane < TWO_R) {
            float* gs = g_sim[b];
            #pragma unroll
            for (int k = 0; k < 7; k++) {
                int i = i0 + k;
                if (i < TWO_R)
                    atomicAdd(&gs[i * TWO_R + lane], acc[k]);
            }
        }
    }

    // ---- Phase 3: acq_rel counter arrive (no block-wide fence) ----
    __syncthreads();
    if (tid == 0)
        s_last = (atom_add_acqrel_gpu(&g_cnt[b], 1u) == NPIX - 1);
    __syncthreads();
    if (!s_last) return;

    // ---- Phase 4 (batch-last): row losses straight from g_sim via ldcg ----
    // warp w handles rows {w, w+16} (w=0..15; w+16<26 only for w<10).
    {
        const float* gs = g_sim[b];
        int jj = (lane < TWO_R) ? lane : 25;
        float dj = __ldcg(gs + 27 * jj);                 // diag[jj]
        float v0r = __ldcg(gs + warp * TWO_R + jj);      // row warp, col jj
        float v1r = (warp + 16 < TWO_R)
                  ? __ldcg(gs + (warp + 16) * TWO_R + jj) : 0.f;
        float rn_j = rsqrtf(fmaxf(dj, 1e-16f));

        float wl = 0.f;
        #pragma unroll
        for (int ri = 0; ri < 2; ri++) {
            int i = warp + ri * 16;
            if (i < TWO_R) {
                float raw = ri ? v1r : v0r;
                float rn_i = __shfl_sync(0xffffffffu, rn_j, i);
                bool valid = (lane < TWO_R) && (lane != i);
                float v = valid ? raw * rn_i * rn_j * TAU_INV : 0.f;
                float e = valid ? __expf(v) : 0.f;
                #pragma unroll
                for (int o = 16; o > 0; o >>= 1)
                    e += __shfl_xor_sync(0xffffffffu, e, o);
                int partner = (i + Rr) % TWO_R;
                float pv = __shfl_sync(0xffffffffu, v, partner);
                if (lane == 0) wl += __logf(e) - pv;
            }
        }
        if (lane == 0) rowloss[warp] = wl;
    }
    __syncthreads();   // orders rowloss AND all phase-4 ldcg before the reset

    // ---- Reset g_sim[b] + counter (after all reads done) ----
    if (tid < SIMN / 4)
        ((float4*)g_sim[b])[tid] = make_float4(0.f, 0.f, 0.f, 0.f);
    if (tid == 1) g_cnt[b] = 0;

    // ---- Phase 5: ONE fused atomic: count in high bits, sum in low ----
    if (tid == 0) {
        float total = 0.f;
        #pragma unroll
        for (int k = 0; k < 16; k++) total += rowloss[k];
        double old = atomicAdd(&g_dsum, (double)total + OFS);
        if (old >= 15.0 * OFS) {               // I'm the 16th finisher
            double full = old + (double)total + OFS - 16.0 * OFS;
            out[0] = (float)(full / (double)(BSZ * TWO_R));
            g_dsum = 0.0;                       // reset for next replay
        }
    }
}

extern "C" void kernel_launch(void* const* d_in, const int* in_sizes, int n_in,
                              void* d_out, int out_size)
{
    const float* f1 = (const float*)d_in[0];
    const float* f2 = (const float*)d_in[1];
    const int*   bi = (const int*)d_in[2];
    const int*   hi = (const int*)d_in[3];
    const int*   wi = (const int*)d_in[4];
    float* out = (float*)d_out;

    infonce_split<<<BSZ * NPIX, 512>>>(f1, f2, bi, hi, wi, out);
}